// round 10
// baseline (speedup 1.0000x reference)
#include <cuda_runtime.h>

#define MAXN 50000
#define MAXE 1000000
#define F_IN 300
#define F_HID 64

typedef unsigned long long ull;

// ---------------- scratch (static device globals; no allocation allowed) ----
__device__ float g_H1[MAXN * 64];
__device__ float g_G [MAXN * 64];
__device__ float g_H2[MAXN * 64];
__device__ float g_ssrc1[MAXN * 8];
__device__ float g_sdst1[MAXN * 8];
__device__ float g_ssrc2[MAXN];
__device__ float g_sdst2[MAXN];
__device__ int   g_cnt[MAXN];
__device__ int   g_rowoff[MAXN + 1];
__device__ int   g_cursor[MAXN];
__device__ int   g_colsrc[MAXE];
__device__ int   g_part[256];
__device__ int   g_partoff[256];
__device__ int   g_idx64;

// ---------------- packed f32x2 helpers ---------------------------------------
__device__ __forceinline__ ull bc2(float x) {
    ull r; unsigned u = __float_as_uint(x);
    asm("mov.b64 %0, {%1, %1};" : "=l"(r) : "r"(u));
    return r;
}
__device__ __forceinline__ void fma2(ull& a, ull x, ull w) {
    asm("fma.rn.f32x2 %0, %1, %2, %0;" : "+l"(a) : "l"(x), "l"(w));
}
__device__ __forceinline__ float2 unpack2(ull a) {
    return make_float2(__uint_as_float((unsigned)a),
                       __uint_as_float((unsigned)(a >> 32)));
}

// ---------------- edge index access (dtype-agnostic) ------------------------
__device__ __forceinline__ int eidx(const void* ei, int pos) {
    if (g_idx64) return (int)((const long long*)ei)[pos];
    return ((const int*)ei)[pos];
}

__global__ void detect_kernel(const int* ei32) {
    if (threadIdx.x == 0 && blockIdx.x == 0) {
        int allz = 1;
        #pragma unroll
        for (int i = 0; i < 16; i++)
            if (ei32[2 * i + 1] != 0) allz = 0;
        g_idx64 = allz;
    }
}

// ---------------- CSR build --------------------------------------------------
__global__ void init_kernel(int N) {
    int i = blockIdx.x * blockDim.x + threadIdx.x;
    if (i < N) { g_cnt[i] = 0; g_cursor[i] = 0; }
}

__global__ void hist_kernel(const void* ei, int E) {
    int i = blockIdx.x * blockDim.x + threadIdx.x;
    if (i < E) {
        int d = eidx(ei, E + i);
        atomicAdd(&g_cnt[d], 1);
    }
}

#define SCAN_BLK 256
__global__ void scan_part_kernel(int N) {
    __shared__ int sh[SCAN_BLK];
    int t = threadIdx.x;
    int i = blockIdx.x * SCAN_BLK + t;
    sh[t] = (i < N) ? g_cnt[i] : 0;
    __syncthreads();
    for (int o = SCAN_BLK / 2; o > 0; o >>= 1) {
        if (t < o) sh[t] += sh[t + o];
        __syncthreads();
    }
    if (t == 0) g_part[blockIdx.x] = sh[0];
}

__global__ void scan_mid_kernel(int nb) {
    __shared__ int sh[SCAN_BLK];
    int t = threadIdx.x;
    int v = (t < nb) ? g_part[t] : 0;
    sh[t] = v;
    __syncthreads();
    for (int o = 1; o < SCAN_BLK; o <<= 1) {
        int u = (t >= o) ? sh[t - o] : 0;
        __syncthreads();
        sh[t] += u;
        __syncthreads();
    }
    g_partoff[t] = sh[t] - v;
}

__global__ void scan_final_kernel(int N, int E) {
    __shared__ int sh[SCAN_BLK];
    int t = threadIdx.x;
    int i = blockIdx.x * SCAN_BLK + t;
    int v = (i < N) ? g_cnt[i] : 0;
    sh[t] = v;
    __syncthreads();
    for (int o = 1; o < SCAN_BLK; o <<= 1) {
        int u = (t >= o) ? sh[t - o] : 0;
        __syncthreads();
        sh[t] += u;
        __syncthreads();
    }
    if (i < N) g_rowoff[i] = g_partoff[blockIdx.x] + sh[t] - v;
    if (i == 0) g_rowoff[N] = E;
}

__global__ void scatter_kernel(const void* ei, int E) {
    int i = blockIdx.x * blockDim.x + threadIdx.x;
    if (i < E) {
        int s = eidx(ei, i);
        int d = eidx(ei, E + i);
        int p = atomicAdd(&g_cursor[d], 1);
        g_colsrc[g_rowoff[d] + p] = s;
    }
}

// ---------------- fused GEMM + attention logits ------------------------------
// H[N,64] = X[N,K] @ W[K,64] + fused per-head scores.
// R=8 rows per warp: the per-k LDS.64 of W is amortized over 8 FFMA2s,
// halving L1/smem wavefront traffic vs R=4 (the R9 bottleneck at L1=72%).
#define GR 8
template <int K, int HEADS>
__global__ void gemm_scores_kernel(const float* __restrict__ X,
                                   const float* __restrict__ W,
                                   const float* __restrict__ avs,
                                   const float* __restrict__ avd,
                                   float* __restrict__ Hout,
                                   float* __restrict__ ssrc,
                                   float* __restrict__ sdst, int N) {
    extern __shared__ float sW[];
    for (int i = threadIdx.x; i < K * 16; i += blockDim.x)
        ((float4*)sW)[i] = ((const float4*)W)[i];
    __syncthreads();

    int gt   = blockIdx.x * blockDim.x + threadIdx.x;
    int warp = gt >> 5;
    int lane = gt & 31;
    int row0 = warp * GR;
    if (row0 >= N) return;

    const float4* xp[GR];
    #pragma unroll
    for (int i = 0; i < GR; i++)
        xp[i] = (const float4*)(X + (size_t)min(row0 + i, N - 1) * K);

    ull acc[GR];
    #pragma unroll
    for (int i = 0; i < GR; i++) acc[i] = 0;

    const ull* wl = (const ull*)sW + lane;

    #pragma unroll 2
    for (int q = 0; q < K / 4; q++) {
        float4 v[GR];
        #pragma unroll
        for (int i = 0; i < GR; i++) v[i] = __ldg(xp[i] + q);
        ull w0 = wl[(4 * q + 0) * 32];
        ull w1 = wl[(4 * q + 1) * 32];
        ull w2 = wl[(4 * q + 2) * 32];
        ull w3 = wl[(4 * q + 3) * 32];
        #pragma unroll
        for (int i = 0; i < GR; i++) {
            fma2(acc[i], bc2(v[i].x), w0);
            fma2(acc[i], bc2(v[i].y), w1);
            fma2(acc[i], bc2(v[i].z), w2);
            fma2(acc[i], bc2(v[i].w), w3);
        }
    }

    float2 as = *(const float2*)(avs + 2 * lane);
    float2 ad = *(const float2*)(avd + 2 * lane);

    #pragma unroll
    for (int i = 0; i < GR; i++) {
        int row = row0 + i;
        if (row >= N) break;
        float2 r = unpack2(acc[i]);
        *(float2*)(Hout + (size_t)row * 64 + 2 * lane) = r;
        float vs = r.x * as.x + r.y * as.y;
        float vd = r.x * ad.x + r.y * ad.y;
        if (HEADS == 8) {
            vs += __shfl_xor_sync(0xffffffffu, vs, 1);
            vd += __shfl_xor_sync(0xffffffffu, vd, 1);
            vs += __shfl_xor_sync(0xffffffffu, vs, 2);
            vd += __shfl_xor_sync(0xffffffffu, vd, 2);
            if ((lane & 3) == 0) {
                ssrc[row * 8 + (lane >> 2)] = vs;
                sdst[row * 8 + (lane >> 2)] = vd;
            }
        } else {
            #pragma unroll
            for (int o = 1; o < 32; o <<= 1) {
                vs += __shfl_xor_sync(0xffffffffu, vs, o);
                vd += __shfl_xor_sync(0xffffffffu, vd, o);
            }
            if (lane == 0) { ssrc[row] = vs; sdst[row] = vd; }
        }
    }
}

// ---------------- segment-softmax + aggregation -------------------------------
#define CAP 64
template <int HEADS, bool ELU>
__global__ void aggregate_kernel(const float* __restrict__ Hf,
                                 const float* __restrict__ ssrc,
                                 const float* __restrict__ sdst,
                                 const float* __restrict__ bias,
                                 float* __restrict__ out, int N) {
    __shared__ float sE[8][CAP * HEADS];
    __shared__ int   sS[8][CAP];
    int gt = blockIdx.x * blockDim.x + threadIdx.x;
    int n = gt >> 5, lane = gt & 31;
    if (n >= N) return;
    int wI = threadIdx.x >> 5;
    int head = (HEADS == 8) ? (lane >> 2) : 0;
    int beg = g_rowoff[n], end = g_rowoff[n + 1];
    int deg = end - beg;
    float* se = sE[wI];
    int*   ss = sS[wI];

    float sw = 0.f, ax = 0.f, ay = 0.f;

    if (deg <= CAP) {
        if (HEADS == 8) {
            float4 d0 = *(const float4*)(sdst + (size_t)n * 8);
            float4 d1 = *(const float4*)(sdst + (size_t)n * 8 + 4);
            #pragma unroll
            for (int base = 0; base < CAP; base += 32) {
                int j = base + lane;
                if (j < deg) {
                    int s = __ldg(&g_colsrc[beg + j]);
                    ss[j] = s;
                    float4 s0 = __ldg((const float4*)(ssrc + (size_t)s * 8));
                    float4 s1 = __ldg((const float4*)(ssrc + (size_t)s * 8 + 4));
                    float e;
                    e = s0.x + d0.x; se[j * 8 + 0] = fmaxf(e, 0.2f * e);
                    e = s0.y + d0.y; se[j * 8 + 1] = fmaxf(e, 0.2f * e);
                    e = s0.z + d0.z; se[j * 8 + 2] = fmaxf(e, 0.2f * e);
                    e = s0.w + d0.w; se[j * 8 + 3] = fmaxf(e, 0.2f * e);
                    e = s1.x + d1.x; se[j * 8 + 4] = fmaxf(e, 0.2f * e);
                    e = s1.y + d1.y; se[j * 8 + 5] = fmaxf(e, 0.2f * e);
                    e = s1.z + d1.z; se[j * 8 + 6] = fmaxf(e, 0.2f * e);
                    e = s1.w + d1.w; se[j * 8 + 7] = fmaxf(e, 0.2f * e);
                }
            }
        } else {
            float sd = __ldg(&sdst[n]);
            #pragma unroll
            for (int base = 0; base < CAP; base += 32) {
                int j = base + lane;
                if (j < deg) {
                    int s = __ldg(&g_colsrc[beg + j]);
                    ss[j] = s;
                    float e = __ldg(&ssrc[s]) + sd;
                    se[j] = fmaxf(e, 0.2f * e);
                }
            }
        }
        __syncwarp();

        float m = -1e30f;
        for (int j = 0; j < deg; j++)
            m = fmaxf(m, se[j * HEADS + head]);

        for (int j = 0; j < deg; j++) {
            float w = __expf(se[j * HEADS + head] - m);
            int s = ss[j];
            float2 hv = *(const float2*)(Hf + (size_t)s * 64 + 2 * lane);
            sw += w;
            ax = fmaf(hv.x, w, ax);
            ay = fmaf(hv.y, w, ay);
        }
    } else {
        float sd = sdst[n * HEADS + head];
        float m = -1e30f;
        for (int j = beg; j < end; j++) {
            int s = __ldg(&g_colsrc[j]);
            float e = __ldg(&ssrc[s * HEADS + head]) + sd;
            m = fmaxf(m, fmaxf(e, 0.2f * e));
        }
        for (int j = beg; j < end; j++) {
            int s = __ldg(&g_colsrc[j]);
            float e = __ldg(&ssrc[s * HEADS + head]) + sd;
            e = fmaxf(e, 0.2f * e);
            float w = __expf(e - m);
            float2 hv = *(const float2*)(Hf + (size_t)s * 64 + 2 * lane);
            sw += w;
            ax = fmaf(hv.x, w, ax);
            ay = fmaf(hv.y, w, ay);
        }
    }

    float inv = 1.f / (sw + 1e-16f);
    float2 bv = *(const float2*)(bias + 2 * lane);
    float o0 = ax * inv + bv.x;
    float o1 = ay * inv + bv.y;
    if (ELU) {
        o0 = (o0 > 0.f) ? o0 : (__expf(o0) - 1.f);
        o1 = (o1 > 0.f) ? o1 : (__expf(o1) - 1.f);
    }
    *(float2*)(out + (size_t)n * 64 + 2 * lane) = make_float2(o0, o1);
}

// ---------------- launch -----------------------------------------------------
extern "C" void kernel_launch(void* const* d_in, const int* in_sizes, int n_in,
                              void* d_out, int out_size) {
    const float* x   = (const float*)d_in[0];
    const void*  ei  = d_in[1];
    const float* W1  = (const float*)d_in[2];
    const float* as1 = (const float*)d_in[3];
    const float* ad1 = (const float*)d_in[4];
    const float* b1  = (const float*)d_in[5];
    const float* W2  = (const float*)d_in[6];
    const float* as2 = (const float*)d_in[7];
    const float* ad2 = (const float*)d_in[8];
    const float* b2  = (const float*)d_in[9];
    float* out = (float*)d_out;

    int N = in_sizes[0] / F_IN;
    int E = in_sizes[1] / 2;

    float *pH1, *pG, *pH2, *pS1s, *pS1d, *pS2s, *pS2d;
    cudaGetSymbolAddress((void**)&pH1,  g_H1);
    cudaGetSymbolAddress((void**)&pG,   g_G);
    cudaGetSymbolAddress((void**)&pH2,  g_H2);
    cudaGetSymbolAddress((void**)&pS1s, g_ssrc1);
    cudaGetSymbolAddress((void**)&pS1d, g_sdst1);
    cudaGetSymbolAddress((void**)&pS2s, g_ssrc2);
    cudaGetSymbolAddress((void**)&pS2d, g_sdst2);

    cudaFuncSetAttribute(gemm_scores_kernel<F_IN, 8>,
                         cudaFuncAttributeMaxDynamicSharedMemorySize,
                         F_IN * 64 * (int)sizeof(float));
    cudaFuncSetAttribute(gemm_scores_kernel<F_HID, 1>,
                         cudaFuncAttributeMaxDynamicSharedMemorySize,
                         F_HID * 64 * (int)sizeof(float));

    const int TB = 256;
    const int GB = 256;   // gemm block: 8 warps x 8 rows = 64 rows/block

    int nodeBlk = (N * 32 + TB - 1) / TB;
    int gemmThr = ((N + GR - 1) / GR) * 32;
    int gemmBlk = (gemmThr + GB - 1) / GB;
    int nb = (N + SCAN_BLK - 1) / SCAN_BLK;

    // Launch order note: the ncu capture lands on the 4th kernel launch, so
    // gemm1 (independent of the CSR chain) is deliberately placed at slot 4.
    detect_kernel<<<1, 32>>>((const int*)ei);                          // 1
    init_kernel<<<(N + TB - 1) / TB, TB>>>(N);                         // 2
    hist_kernel<<<(E + TB - 1) / TB, TB>>>(ei, E);                     // 3
    gemm_scores_kernel<F_IN, 8><<<gemmBlk, GB, F_IN * 64 * sizeof(float)>>>(
        x, W1, as1, ad1, pH1, pS1s, pS1d, N);                          // 4 <- profiled
    scan_part_kernel<<<nb, SCAN_BLK>>>(N);                             // 5
    scan_mid_kernel<<<1, SCAN_BLK>>>(nb);                              // 6
    scan_final_kernel<<<nb, SCAN_BLK>>>(N, E);                         // 7
    scatter_kernel<<<(E + TB - 1) / TB, TB>>>(ei, E);                  // 8
    aggregate_kernel<8, true><<<nodeBlk, TB>>>(pH1, pS1s, pS1d, b1, pG, N);   // 9
    gemm_scores_kernel<F_HID, 1><<<gemmBlk, GB, F_HID * 64 * sizeof(float)>>>(
        pG, W2, as2, ad2, pH2, pS2s, pS2d, N);                         // 10
    aggregate_kernel<1, false><<<nodeBlk, TB>>>(pH2, pS2s, pS2d, b2, out, N); // 11
}

// round 11
// speedup vs baseline: 1.3504x; 1.3504x over previous
#include <cuda_runtime.h>

#define MAXN 50000
#define MAXE 1000000
#define F_IN 300
#define F_HID 64

typedef unsigned long long ull;

// ---------------- scratch (static device globals; no allocation allowed) ----
__device__ float g_H1[MAXN * 64];
__device__ float g_G [MAXN * 64];
__device__ float g_H2[MAXN * 64];
__device__ float g_ssrc1[MAXN * 8];
__device__ float g_sdst1[MAXN * 8];
__device__ float g_ssrc2[MAXN];
__device__ float g_sdst2[MAXN];
__device__ int   g_cnt[MAXN];
__device__ int   g_rowoff[MAXN + 1];
__device__ int   g_cursor[MAXN];
__device__ int   g_colsrc[MAXE];
__device__ int   g_part[256];
__device__ int   g_partoff[256];
__device__ int   g_idx64;

// ---------------- packed f32x2 helpers ---------------------------------------
__device__ __forceinline__ ull bc2(float x) {
    ull r; unsigned u = __float_as_uint(x);
    asm("mov.b64 %0, {%1, %1};" : "=l"(r) : "r"(u));
    return r;
}
__device__ __forceinline__ void fma2(ull& a, ull x, ull w) {
    asm("fma.rn.f32x2 %0, %1, %2, %0;" : "+l"(a) : "l"(x), "l"(w));
}
__device__ __forceinline__ float2 unpack2(ull a) {
    return make_float2(__uint_as_float((unsigned)a),
                       __uint_as_float((unsigned)(a >> 32)));
}

// ---------------- cp.async helpers -------------------------------------------
__device__ __forceinline__ unsigned su32(const void* p) {
    return (unsigned)__cvta_generic_to_shared(p);
}
__device__ __forceinline__ void cpa16(unsigned dst, const void* src) {
    asm volatile("cp.async.cg.shared.global [%0], [%1], 16;" :: "r"(dst), "l"(src));
}
__device__ __forceinline__ void cpa_commit() {
    asm volatile("cp.async.commit_group;");
}
template <int n>
__device__ __forceinline__ void cpa_wait() {
    asm volatile("cp.async.wait_group %0;" :: "n"(n));
}

// ---------------- edge index access (dtype-agnostic) ------------------------
__device__ __forceinline__ int eidx(const void* ei, int pos) {
    if (g_idx64) return (int)((const long long*)ei)[pos];
    return ((const int*)ei)[pos];
}

__global__ void detect_kernel(const int* ei32) {
    if (threadIdx.x == 0 && blockIdx.x == 0) {
        int allz = 1;
        #pragma unroll
        for (int i = 0; i < 16; i++)
            if (ei32[2 * i + 1] != 0) allz = 0;
        g_idx64 = allz;
    }
}

// ---------------- CSR build --------------------------------------------------
__global__ void init_kernel(int N) {
    int i = blockIdx.x * blockDim.x + threadIdx.x;
    if (i < N) { g_cnt[i] = 0; g_cursor[i] = 0; }
}

__global__ void hist_kernel(const void* ei, int E) {
    int i = blockIdx.x * blockDim.x + threadIdx.x;
    if (i < E) {
        int d = eidx(ei, E + i);
        atomicAdd(&g_cnt[d], 1);
    }
}

#define SCAN_BLK 256
__global__ void scan_part_kernel(int N) {
    __shared__ int sh[SCAN_BLK];
    int t = threadIdx.x;
    int i = blockIdx.x * SCAN_BLK + t;
    sh[t] = (i < N) ? g_cnt[i] : 0;
    __syncthreads();
    for (int o = SCAN_BLK / 2; o > 0; o >>= 1) {
        if (t < o) sh[t] += sh[t + o];
        __syncthreads();
    }
    if (t == 0) g_part[blockIdx.x] = sh[0];
}

__global__ void scan_mid_kernel(int nb) {
    __shared__ int sh[SCAN_BLK];
    int t = threadIdx.x;
    int v = (t < nb) ? g_part[t] : 0;
    sh[t] = v;
    __syncthreads();
    for (int o = 1; o < SCAN_BLK; o <<= 1) {
        int u = (t >= o) ? sh[t - o] : 0;
        __syncthreads();
        sh[t] += u;
        __syncthreads();
    }
    g_partoff[t] = sh[t] - v;
}

__global__ void scan_final_kernel(int N, int E) {
    __shared__ int sh[SCAN_BLK];
    int t = threadIdx.x;
    int i = blockIdx.x * SCAN_BLK + t;
    int v = (i < N) ? g_cnt[i] : 0;
    sh[t] = v;
    __syncthreads();
    for (int o = 1; o < SCAN_BLK; o <<= 1) {
        int u = (t >= o) ? sh[t - o] : 0;
        __syncthreads();
        sh[t] += u;
        __syncthreads();
    }
    if (i < N) g_rowoff[i] = g_partoff[blockIdx.x] + sh[t] - v;
    if (i == 0) g_rowoff[N] = E;
}

__global__ void scatter_kernel(const void* ei, int E) {
    int i = blockIdx.x * blockDim.x + threadIdx.x;
    if (i < E) {
        int s = eidx(ei, i);
        int d = eidx(ei, E + i);
        int p = atomicAdd(&g_cursor[d], 1);
        g_colsrc[g_rowoff[d] + p] = s;
    }
}

// ---------------- pipelined GEMM + attention logits ---------------------------
// H[N,64] = X[N,K] @ W[K,64] + fused per-head scores.
// 512 threads / block, 128 rows / block (8 rows per warp).
// x streamed through a 3-stage cp.async pipeline (32-k chunks, 16KB/stage) so
// DRAM latency is fully covered; W async-loaded into smem in group 0.
// Compute reads x via broadcast LDS.128 and W via LDS.64; packed FFMA2 MACs.
#define GSTG 3
#define RBLK 128
template <int K, int HEADS>
__global__ __launch_bounds__(512, 1)
void gemm_scores_kernel(const float* __restrict__ X,
                        const float* __restrict__ W,
                        const float* __restrict__ avs,
                        const float* __restrict__ avd,
                        float* __restrict__ Hout,
                        float* __restrict__ ssrc,
                        float* __restrict__ sdst, int N) {
    constexpr int NC = (K + 31) / 32;                  // 32-k chunks
    extern __shared__ float smem[];
    float*  sW = smem;                                 // K*64 floats
    float4* sX = (float4*)(smem + K * 64);             // [GSTG][RBLK][8]

    int tid = threadIdx.x;
    int rowBase = blockIdx.x * RBLK;

    // W async load (joins commit group 0)
    for (int i = tid; i < K * 16; i += 512)
        cpa16(su32(sW) + i * 16, (const char*)W + (size_t)i * 16);

    // x stage loader: thread t covers row t/4, float4 pair (t%4)*2, +1
    int lr  = tid >> 2;
    int sub = tid & 3;
    const char* xrow = (const char*)(X + (size_t)min(rowBase + lr, N - 1) * K);
    unsigned sxb = su32(sX);

    auto load_stage = [&](int s) {
        int kb  = s * 32;
        int nf4 = min(8, (K - kb + 3) >> 2);
        unsigned dst = sxb + (unsigned)(((s % GSTG) * RBLK + lr) * 8) * 16u;
        #pragma unroll
        for (int jj = 0; jj < 2; jj++) {
            int j = sub * 2 + jj;
            if (j < nf4) cpa16(dst + j * 16, xrow + (size_t)kb * 4 + j * 16);
        }
    };

    #pragma unroll
    for (int s = 0; s < GSTG; s++) {
        if (s < NC) load_stage(s);
        cpa_commit();
    }

    int warp = tid >> 5, lane = tid & 31;
    int row0 = rowBase + warp * 8;
    bool active = row0 < N;

    ull acc[8];
    #pragma unroll
    for (int i = 0; i < 8; i++) acc[i] = 0;
    const ull* wl = (const ull*)sW + lane;

    for (int c = 0; c < NC; c++) {
        cpa_wait<GSTG - 1>();          // oldest group (chunk c [+W if c==0]) done
        __syncthreads();
        if (active) {
            int kb = c * 32;
            int nq = min(8, (K - kb) >> 2);    // quads in this chunk
            const float4* sxs = sX + ((c % GSTG) * RBLK + warp * 8) * 8;
            for (int q = 0; q < nq; q++) {
                int k0 = kb + 4 * q;
                ull w0 = wl[(k0 + 0) * 32];
                ull w1 = wl[(k0 + 1) * 32];
                ull w2 = wl[(k0 + 2) * 32];
                ull w3 = wl[(k0 + 3) * 32];
                #pragma unroll
                for (int i = 0; i < 8; i++) {
                    float4 v = sxs[i * 8 + q];
                    fma2(acc[i], bc2(v.x), w0);
                    fma2(acc[i], bc2(v.y), w1);
                    fma2(acc[i], bc2(v.z), w2);
                    fma2(acc[i], bc2(v.w), w3);
                }
            }
        }
        __syncthreads();               // slot (c%GSTG) free for reuse
        int s = c + GSTG;
        if (s < NC) load_stage(s);
        cpa_commit();                  // exactly one group per iteration
    }

    if (!active) return;
    float2 as = *(const float2*)(avs + 2 * lane);
    float2 ad = *(const float2*)(avd + 2 * lane);

    #pragma unroll
    for (int i = 0; i < 8; i++) {
        int row = row0 + i;
        if (row >= N) break;
        float2 r = unpack2(acc[i]);
        *(float2*)(Hout + (size_t)row * 64 + 2 * lane) = r;
        float vs = r.x * as.x + r.y * as.y;
        float vd = r.x * ad.x + r.y * ad.y;
        if (HEADS == 8) {
            vs += __shfl_xor_sync(0xffffffffu, vs, 1);
            vd += __shfl_xor_sync(0xffffffffu, vd, 1);
            vs += __shfl_xor_sync(0xffffffffu, vs, 2);
            vd += __shfl_xor_sync(0xffffffffu, vd, 2);
            if ((lane & 3) == 0) {
                ssrc[row * 8 + (lane >> 2)] = vs;
                sdst[row * 8 + (lane >> 2)] = vd;
            }
        } else {
            #pragma unroll
            for (int o = 1; o < 32; o <<= 1) {
                vs += __shfl_xor_sync(0xffffffffu, vs, o);
                vd += __shfl_xor_sync(0xffffffffu, vd, o);
            }
            if (lane == 0) { ssrc[row] = vs; sdst[row] = vd; }
        }
    }
}

// ---------------- segment-softmax + aggregation -------------------------------
#define CAP 64
template <int HEADS, bool ELU>
__global__ void aggregate_kernel(const float* __restrict__ Hf,
                                 const float* __restrict__ ssrc,
                                 const float* __restrict__ sdst,
                                 const float* __restrict__ bias,
                                 float* __restrict__ out, int N) {
    __shared__ float sE[8][CAP * HEADS];
    __shared__ int   sS[8][CAP];
    int gt = blockIdx.x * blockDim.x + threadIdx.x;
    int n = gt >> 5, lane = gt & 31;
    if (n >= N) return;
    int wI = threadIdx.x >> 5;
    int head = (HEADS == 8) ? (lane >> 2) : 0;
    int beg = g_rowoff[n], end = g_rowoff[n + 1];
    int deg = end - beg;
    float* se = sE[wI];
    int*   ss = sS[wI];

    float sw = 0.f, ax = 0.f, ay = 0.f;

    if (deg <= CAP) {
        if (HEADS == 8) {
            float4 d0 = *(const float4*)(sdst + (size_t)n * 8);
            float4 d1 = *(const float4*)(sdst + (size_t)n * 8 + 4);
            #pragma unroll
            for (int base = 0; base < CAP; base += 32) {
                int j = base + lane;
                if (j < deg) {
                    int s = __ldg(&g_colsrc[beg + j]);
                    ss[j] = s;
                    float4 s0 = __ldg((const float4*)(ssrc + (size_t)s * 8));
                    float4 s1 = __ldg((const float4*)(ssrc + (size_t)s * 8 + 4));
                    float e;
                    e = s0.x + d0.x; se[j * 8 + 0] = fmaxf(e, 0.2f * e);
                    e = s0.y + d0.y; se[j * 8 + 1] = fmaxf(e, 0.2f * e);
                    e = s0.z + d0.z; se[j * 8 + 2] = fmaxf(e, 0.2f * e);
                    e = s0.w + d0.w; se[j * 8 + 3] = fmaxf(e, 0.2f * e);
                    e = s1.x + d1.x; se[j * 8 + 4] = fmaxf(e, 0.2f * e);
                    e = s1.y + d1.y; se[j * 8 + 5] = fmaxf(e, 0.2f * e);
                    e = s1.z + d1.z; se[j * 8 + 6] = fmaxf(e, 0.2f * e);
                    e = s1.w + d1.w; se[j * 8 + 7] = fmaxf(e, 0.2f * e);
                }
            }
        } else {
            float sd = __ldg(&sdst[n]);
            #pragma unroll
            for (int base = 0; base < CAP; base += 32) {
                int j = base + lane;
                if (j < deg) {
                    int s = __ldg(&g_colsrc[beg + j]);
                    ss[j] = s;
                    float e = __ldg(&ssrc[s]) + sd;
                    se[j] = fmaxf(e, 0.2f * e);
                }
            }
        }
        __syncwarp();

        float m = -1e30f;
        for (int j = 0; j < deg; j++)
            m = fmaxf(m, se[j * HEADS + head]);

        for (int j = 0; j < deg; j++) {
            float w = __expf(se[j * HEADS + head] - m);
            int s = ss[j];
            float2 hv = *(const float2*)(Hf + (size_t)s * 64 + 2 * lane);
            sw += w;
            ax = fmaf(hv.x, w, ax);
            ay = fmaf(hv.y, w, ay);
        }
    } else {
        float sd = sdst[n * HEADS + head];
        float m = -1e30f;
        for (int j = beg; j < end; j++) {
            int s = __ldg(&g_colsrc[j]);
            float e = __ldg(&ssrc[s * HEADS + head]) + sd;
            m = fmaxf(m, fmaxf(e, 0.2f * e));
        }
        for (int j = beg; j < end; j++) {
            int s = __ldg(&g_colsrc[j]);
            float e = __ldg(&ssrc[s * HEADS + head]) + sd;
            e = fmaxf(e, 0.2f * e);
            float w = __expf(e - m);
            float2 hv = *(const float2*)(Hf + (size_t)s * 64 + 2 * lane);
            sw += w;
            ax = fmaf(hv.x, w, ax);
            ay = fmaf(hv.y, w, ay);
        }
    }

    float inv = 1.f / (sw + 1e-16f);
    float2 bv = *(const float2*)(bias + 2 * lane);
    float o0 = ax * inv + bv.x;
    float o1 = ay * inv + bv.y;
    if (ELU) {
        o0 = (o0 > 0.f) ? o0 : (__expf(o0) - 1.f);
        o1 = (o1 > 0.f) ? o1 : (__expf(o1) - 1.f);
    }
    *(float2*)(out + (size_t)n * 64 + 2 * lane) = make_float2(o0, o1);
}

// ---------------- launch -----------------------------------------------------
extern "C" void kernel_launch(void* const* d_in, const int* in_sizes, int n_in,
                              void* d_out, int out_size) {
    const float* x   = (const float*)d_in[0];
    const void*  ei  = d_in[1];
    const float* W1  = (const float*)d_in[2];
    const float* as1 = (const float*)d_in[3];
    const float* ad1 = (const float*)d_in[4];
    const float* b1  = (const float*)d_in[5];
    const float* W2  = (const float*)d_in[6];
    const float* as2 = (const float*)d_in[7];
    const float* ad2 = (const float*)d_in[8];
    const float* b2  = (const float*)d_in[9];
    float* out = (float*)d_out;

    int N = in_sizes[0] / F_IN;
    int E = in_sizes[1] / 2;

    float *pH1, *pG, *pH2, *pS1s, *pS1d, *pS2s, *pS2d;
    cudaGetSymbolAddress((void**)&pH1,  g_H1);
    cudaGetSymbolAddress((void**)&pG,   g_G);
    cudaGetSymbolAddress((void**)&pH2,  g_H2);
    cudaGetSymbolAddress((void**)&pS1s, g_ssrc1);
    cudaGetSymbolAddress((void**)&pS1d, g_sdst1);
    cudaGetSymbolAddress((void**)&pS2s, g_ssrc2);
    cudaGetSymbolAddress((void**)&pS2d, g_sdst2);

    const int SM1 = F_IN  * 64 * 4 + GSTG * RBLK * 8 * 16;   // 125952 B
    const int SM2 = F_HID * 64 * 4 + GSTG * RBLK * 8 * 16;   //  65536 B
    cudaFuncSetAttribute(gemm_scores_kernel<F_IN, 8>,
                         cudaFuncAttributeMaxDynamicSharedMemorySize, SM1);
    cudaFuncSetAttribute(gemm_scores_kernel<F_HID, 1>,
                         cudaFuncAttributeMaxDynamicSharedMemorySize, SM2);

    const int TB = 256;

    int nodeBlk = (N * 32 + TB - 1) / TB;
    int gemmBlk = (N + RBLK - 1) / RBLK;
    int nb = (N + SCAN_BLK - 1) / SCAN_BLK;

    // Launch order note: the ncu capture lands on the 4th kernel launch, so
    // gemm1 (independent of the CSR chain) is deliberately placed at slot 4.
    detect_kernel<<<1, 32>>>((const int*)ei);                          // 1
    init_kernel<<<(N + TB - 1) / TB, TB>>>(N);                         // 2
    hist_kernel<<<(E + TB - 1) / TB, TB>>>(ei, E);                     // 3
    gemm_scores_kernel<F_IN, 8><<<gemmBlk, 512, SM1>>>(
        x, W1, as1, ad1, pH1, pS1s, pS1d, N);                          // 4 <- profiled
    scan_part_kernel<<<nb, SCAN_BLK>>>(N);                             // 5
    scan_mid_kernel<<<1, SCAN_BLK>>>(nb);                              // 6
    scan_final_kernel<<<nb, SCAN_BLK>>>(N, E);                         // 7
    scatter_kernel<<<(E + TB - 1) / TB, TB>>>(ei, E);                  // 8
    aggregate_kernel<8, true><<<nodeBlk, TB>>>(pH1, pS1s, pS1d, b1, pG, N);   // 9
    gemm_scores_kernel<F_HID, 1><<<gemmBlk, 512, SM2>>>(
        pG, W2, as2, ad2, pH2, pS2s, pS2d, N);                         // 10
    aggregate_kernel<1, false><<<nodeBlk, TB>>>(pH2, pS2s, pS2d, b2, out, N); // 11
}

// round 12
// speedup vs baseline: 1.4290x; 1.0582x over previous
#include <cuda_runtime.h>

#define MAXN 50000
#define MAXE 1000000
#define F_IN 300
#define F_HID 64

typedef unsigned long long ull;

// ---------------- scratch (static device globals; no allocation allowed) ----
__device__ float g_H1[MAXN * 64];
__device__ float g_G [MAXN * 64];
__device__ float g_H2[MAXN * 64];
__device__ float g_ssrc1[MAXN * 8];
__device__ float g_sdst1[MAXN * 8];
__device__ float g_ssrc2[MAXN];
__device__ float g_sdst2[MAXN];
__device__ int   g_cnt[MAXN];
__device__ int   g_rowoff[MAXN + 1];
__device__ int   g_cursor[MAXN];
__device__ int   g_colsrc[MAXE];
__device__ int   g_part[256];
__device__ int   g_partoff[256];
__device__ int   g_idx64;

// ---------------- packed f32x2 helpers ---------------------------------------
__device__ __forceinline__ ull bc2(float x) {
    ull r; unsigned u = __float_as_uint(x);
    asm("mov.b64 %0, {%1, %1};" : "=l"(r) : "r"(u));
    return r;
}
__device__ __forceinline__ void fma2(ull& a, ull x, ull w) {
    asm("fma.rn.f32x2 %0, %1, %2, %0;" : "+l"(a) : "l"(x), "l"(w));
}
__device__ __forceinline__ float2 unpack2(ull a) {
    return make_float2(__uint_as_float((unsigned)a),
                       __uint_as_float((unsigned)(a >> 32)));
}

// ---------------- cp.async helpers -------------------------------------------
__device__ __forceinline__ unsigned su32(const void* p) {
    return (unsigned)__cvta_generic_to_shared(p);
}
__device__ __forceinline__ void cpa16(unsigned dst, const void* src) {
    asm volatile("cp.async.cg.shared.global [%0], [%1], 16;" :: "r"(dst), "l"(src));
}
__device__ __forceinline__ void cpa_commit() {
    asm volatile("cp.async.commit_group;");
}
template <int n>
__device__ __forceinline__ void cpa_wait() {
    asm volatile("cp.async.wait_group %0;" :: "n"(n));
}

// ---------------- edge index access (dtype-agnostic) ------------------------
__device__ __forceinline__ int eidx(const void* ei, int pos) {
    if (g_idx64) return (int)((const long long*)ei)[pos];
    return ((const int*)ei)[pos];
}

__global__ void detect_kernel(const int* ei32) {
    if (threadIdx.x == 0 && blockIdx.x == 0) {
        int allz = 1;
        #pragma unroll
        for (int i = 0; i < 16; i++)
            if (ei32[2 * i + 1] != 0) allz = 0;
        g_idx64 = allz;
    }
}

// ---------------- CSR build --------------------------------------------------
__global__ void init_kernel(int N) {
    int i = blockIdx.x * blockDim.x + threadIdx.x;
    if (i < N) { g_cnt[i] = 0; g_cursor[i] = 0; }
}

__global__ void hist_kernel(const void* ei, int E) {
    int i = blockIdx.x * blockDim.x + threadIdx.x;
    if (i < E) {
        int d = eidx(ei, E + i);
        atomicAdd(&g_cnt[d], 1);
    }
}

#define SCAN_BLK 256
__global__ void scan_part_kernel(int N) {
    __shared__ int sh[SCAN_BLK];
    int t = threadIdx.x;
    int i = blockIdx.x * SCAN_BLK + t;
    sh[t] = (i < N) ? g_cnt[i] : 0;
    __syncthreads();
    for (int o = SCAN_BLK / 2; o > 0; o >>= 1) {
        if (t < o) sh[t] += sh[t + o];
        __syncthreads();
    }
    if (t == 0) g_part[blockIdx.x] = sh[0];
}

__global__ void scan_mid_kernel(int nb) {
    __shared__ int sh[SCAN_BLK];
    int t = threadIdx.x;
    int v = (t < nb) ? g_part[t] : 0;
    sh[t] = v;
    __syncthreads();
    for (int o = 1; o < SCAN_BLK; o <<= 1) {
        int u = (t >= o) ? sh[t - o] : 0;
        __syncthreads();
        sh[t] += u;
        __syncthreads();
    }
    g_partoff[t] = sh[t] - v;
}

__global__ void scan_final_kernel(int N, int E) {
    __shared__ int sh[SCAN_BLK];
    int t = threadIdx.x;
    int i = blockIdx.x * SCAN_BLK + t;
    int v = (i < N) ? g_cnt[i] : 0;
    sh[t] = v;
    __syncthreads();
    for (int o = 1; o < SCAN_BLK; o <<= 1) {
        int u = (t >= o) ? sh[t - o] : 0;
        __syncthreads();
        sh[t] += u;
        __syncthreads();
    }
    if (i < N) g_rowoff[i] = g_partoff[blockIdx.x] + sh[t] - v;
    if (i == 0) g_rowoff[N] = E;
}

__global__ void scatter_kernel(const void* ei, int E) {
    int i = blockIdx.x * blockDim.x + threadIdx.x;
    if (i < E) {
        int s = eidx(ei, i);
        int d = eidx(ei, E + i);
        int p = atomicAdd(&g_cursor[d], 1);
        g_colsrc[g_rowoff[d] + p] = s;
    }
}

// ---------------- pipelined GEMM + attention logits ---------------------------
// H[N,64] = X[N,K] @ W[K,64] + fused per-head scores.
// 512 threads / block, 128 rows / block (8 rows per warp).
// GSTG=2 (smem 107KB) + __launch_bounds__(512,2) + interleaved per-row inner
// loop (live regs ~40) => 2 blocks/SM = 32 warps/SM, double the R11 occupancy.
#define GSTG 2
#define RBLK 128
template <int K, int HEADS>
__global__ __launch_bounds__(512, 2)
void gemm_scores_kernel(const float* __restrict__ X,
                        const float* __restrict__ W,
                        const float* __restrict__ avs,
                        const float* __restrict__ avd,
                        float* __restrict__ Hout,
                        float* __restrict__ ssrc,
                        float* __restrict__ sdst, int N) {
    constexpr int NC = (K + 31) / 32;                  // 32-k chunks
    extern __shared__ float smem[];
    float*  sW = smem;                                 // K*64 floats
    float4* sX = (float4*)(smem + K * 64);             // [GSTG][RBLK][8]

    int tid = threadIdx.x;
    int rowBase = blockIdx.x * RBLK;

    // W async load (joins commit group 0)
    for (int i = tid; i < K * 16; i += 512)
        cpa16(su32(sW) + i * 16, (const char*)W + (size_t)i * 16);

    // x stage loader: thread t covers row t/4, float4 pair (t%4)*2, +1
    int lr  = tid >> 2;
    int sub = tid & 3;
    const char* xrow = (const char*)(X + (size_t)min(rowBase + lr, N - 1) * K);
    unsigned sxb = su32(sX);

    auto load_stage = [&](int s) {
        int kb  = s * 32;
        int nf4 = min(8, (K - kb + 3) >> 2);
        unsigned dst = sxb + (unsigned)(((s % GSTG) * RBLK + lr) * 8) * 16u;
        #pragma unroll
        for (int jj = 0; jj < 2; jj++) {
            int j = sub * 2 + jj;
            if (j < nf4) cpa16(dst + j * 16, xrow + (size_t)kb * 4 + j * 16);
        }
    };

    #pragma unroll
    for (int s = 0; s < GSTG; s++) {
        if (s < NC) load_stage(s);
        cpa_commit();
    }

    int warp = tid >> 5, lane = tid & 31;
    int row0 = rowBase + warp * 8;
    bool active = row0 < N;

    ull acc[8];
    #pragma unroll
    for (int i = 0; i < 8; i++) acc[i] = 0;
    const ull* wl = (const ull*)sW + lane;

    for (int c = 0; c < NC; c++) {
        cpa_wait<GSTG - 1>();          // oldest group (chunk c [+W if c==0]) done
        __syncthreads();
        if (active) {
            int kb = c * 32;
            int nq = min(8, (K - kb) >> 2);    // quads in this chunk
            const float4* sxs = sX + ((c % GSTG) * RBLK + warp * 8) * 8;
            #pragma unroll 2
            for (int q = 0; q < nq; q++) {
                int k0 = kb + 4 * q;
                ull w0 = wl[(k0 + 0) * 32];
                ull w1 = wl[(k0 + 1) * 32];
                ull w2 = wl[(k0 + 2) * 32];
                ull w3 = wl[(k0 + 3) * 32];
                // per-row interleave: one LDS.128 + 4 FFMA2, small live set
                #pragma unroll
                for (int i = 0; i < 8; i++) {
                    float4 v = sxs[i * 8 + q];
                    fma2(acc[i], bc2(v.x), w0);
                    fma2(acc[i], bc2(v.y), w1);
                    fma2(acc[i], bc2(v.z), w2);
                    fma2(acc[i], bc2(v.w), w3);
                }
            }
        }
        __syncthreads();               // slot (c%GSTG) free for reuse
        int s = c + GSTG;
        if (s < NC) load_stage(s);
        cpa_commit();                  // exactly one group per iteration
    }

    if (!active) return;
    float2 as = *(const float2*)(avs + 2 * lane);
    float2 ad = *(const float2*)(avd + 2 * lane);

    #pragma unroll
    for (int i = 0; i < 8; i++) {
        int row = row0 + i;
        if (row >= N) break;
        float2 r = unpack2(acc[i]);
        *(float2*)(Hout + (size_t)row * 64 + 2 * lane) = r;
        float vs = r.x * as.x + r.y * as.y;
        float vd = r.x * ad.x + r.y * ad.y;
        if (HEADS == 8) {
            vs += __shfl_xor_sync(0xffffffffu, vs, 1);
            vd += __shfl_xor_sync(0xffffffffu, vd, 1);
            vs += __shfl_xor_sync(0xffffffffu, vs, 2);
            vd += __shfl_xor_sync(0xffffffffu, vd, 2);
            if ((lane & 3) == 0) {
                ssrc[row * 8 + (lane >> 2)] = vs;
                sdst[row * 8 + (lane >> 2)] = vd;
            }
        } else {
            #pragma unroll
            for (int o = 1; o < 32; o <<= 1) {
                vs += __shfl_xor_sync(0xffffffffu, vs, o);
                vd += __shfl_xor_sync(0xffffffffu, vd, o);
            }
            if (lane == 0) { ssrc[row] = vs; sdst[row] = vd; }
        }
    }
}

// ---------------- segment-softmax + aggregation -------------------------------
#define CAP 64
template <int HEADS, bool ELU>
__global__ void aggregate_kernel(const float* __restrict__ Hf,
                                 const float* __restrict__ ssrc,
                                 const float* __restrict__ sdst,
                                 const float* __restrict__ bias,
                                 float* __restrict__ out, int N) {
    __shared__ float sE[8][CAP * HEADS];
    __shared__ int   sS[8][CAP];
    int gt = blockIdx.x * blockDim.x + threadIdx.x;
    int n = gt >> 5, lane = gt & 31;
    if (n >= N) return;
    int wI = threadIdx.x >> 5;
    int head = (HEADS == 8) ? (lane >> 2) : 0;
    int beg = g_rowoff[n], end = g_rowoff[n + 1];
    int deg = end - beg;
    float* se = sE[wI];
    int*   ss = sS[wI];

    float sw = 0.f, ax = 0.f, ay = 0.f;

    if (deg <= CAP) {
        if (HEADS == 8) {
            float4 d0 = *(const float4*)(sdst + (size_t)n * 8);
            float4 d1 = *(const float4*)(sdst + (size_t)n * 8 + 4);
            #pragma unroll
            for (int base = 0; base < CAP; base += 32) {
                int j = base + lane;
                if (j < deg) {
                    int s = __ldg(&g_colsrc[beg + j]);
                    ss[j] = s;
                    float4 s0 = __ldg((const float4*)(ssrc + (size_t)s * 8));
                    float4 s1 = __ldg((const float4*)(ssrc + (size_t)s * 8 + 4));
                    float e;
                    e = s0.x + d0.x; se[j * 8 + 0] = fmaxf(e, 0.2f * e);
                    e = s0.y + d0.y; se[j * 8 + 1] = fmaxf(e, 0.2f * e);
                    e = s0.z + d0.z; se[j * 8 + 2] = fmaxf(e, 0.2f * e);
                    e = s0.w + d0.w; se[j * 8 + 3] = fmaxf(e, 0.2f * e);
                    e = s1.x + d1.x; se[j * 8 + 4] = fmaxf(e, 0.2f * e);
                    e = s1.y + d1.y; se[j * 8 + 5] = fmaxf(e, 0.2f * e);
                    e = s1.z + d1.z; se[j * 8 + 6] = fmaxf(e, 0.2f * e);
                    e = s1.w + d1.w; se[j * 8 + 7] = fmaxf(e, 0.2f * e);
                }
            }
        } else {
            float sd = __ldg(&sdst[n]);
            #pragma unroll
            for (int base = 0; base < CAP; base += 32) {
                int j = base + lane;
                if (j < deg) {
                    int s = __ldg(&g_colsrc[beg + j]);
                    ss[j] = s;
                    float e = __ldg(&ssrc[s]) + sd;
                    se[j] = fmaxf(e, 0.2f * e);
                }
            }
        }
        __syncwarp();

        float m = -1e30f;
        for (int j = 0; j < deg; j++)
            m = fmaxf(m, se[j * HEADS + head]);

        for (int j = 0; j < deg; j++) {
            float w = __expf(se[j * HEADS + head] - m);
            int s = ss[j];
            float2 hv = *(const float2*)(Hf + (size_t)s * 64 + 2 * lane);
            sw += w;
            ax = fmaf(hv.x, w, ax);
            ay = fmaf(hv.y, w, ay);
        }
    } else {
        float sd = sdst[n * HEADS + head];
        float m = -1e30f;
        for (int j = beg; j < end; j++) {
            int s = __ldg(&g_colsrc[j]);
            float e = __ldg(&ssrc[s * HEADS + head]) + sd;
            m = fmaxf(m, fmaxf(e, 0.2f * e));
        }
        for (int j = beg; j < end; j++) {
            int s = __ldg(&g_colsrc[j]);
            float e = __ldg(&ssrc[s * HEADS + head]) + sd;
            e = fmaxf(e, 0.2f * e);
            float w = __expf(e - m);
            float2 hv = *(const float2*)(Hf + (size_t)s * 64 + 2 * lane);
            sw += w;
            ax = fmaf(hv.x, w, ax);
            ay = fmaf(hv.y, w, ay);
        }
    }

    float inv = 1.f / (sw + 1e-16f);
    float2 bv = *(const float2*)(bias + 2 * lane);
    float o0 = ax * inv + bv.x;
    float o1 = ay * inv + bv.y;
    if (ELU) {
        o0 = (o0 > 0.f) ? o0 : (__expf(o0) - 1.f);
        o1 = (o1 > 0.f) ? o1 : (__expf(o1) - 1.f);
    }
    *(float2*)(out + (size_t)n * 64 + 2 * lane) = make_float2(o0, o1);
}

// ---------------- launch -----------------------------------------------------
extern "C" void kernel_launch(void* const* d_in, const int* in_sizes, int n_in,
                              void* d_out, int out_size) {
    const float* x   = (const float*)d_in[0];
    const void*  ei  = d_in[1];
    const float* W1  = (const float*)d_in[2];
    const float* as1 = (const float*)d_in[3];
    const float* ad1 = (const float*)d_in[4];
    const float* b1  = (const float*)d_in[5];
    const float* W2  = (const float*)d_in[6];
    const float* as2 = (const float*)d_in[7];
    const float* ad2 = (const float*)d_in[8];
    const float* b2  = (const float*)d_in[9];
    float* out = (float*)d_out;

    int N = in_sizes[0] / F_IN;
    int E = in_sizes[1] / 2;

    float *pH1, *pG, *pH2, *pS1s, *pS1d, *pS2s, *pS2d;
    cudaGetSymbolAddress((void**)&pH1,  g_H1);
    cudaGetSymbolAddress((void**)&pG,   g_G);
    cudaGetSymbolAddress((void**)&pH2,  g_H2);
    cudaGetSymbolAddress((void**)&pS1s, g_ssrc1);
    cudaGetSymbolAddress((void**)&pS1d, g_sdst1);
    cudaGetSymbolAddress((void**)&pS2s, g_ssrc2);
    cudaGetSymbolAddress((void**)&pS2d, g_sdst2);

    const int SM1 = F_IN  * 64 * 4 + GSTG * RBLK * 8 * 16;   // 109568 B
    const int SM2 = F_HID * 64 * 4 + GSTG * RBLK * 8 * 16;   //  49152 B
    cudaFuncSetAttribute(gemm_scores_kernel<F_IN, 8>,
                         cudaFuncAttributeMaxDynamicSharedMemorySize, SM1);
    cudaFuncSetAttribute(gemm_scores_kernel<F_HID, 1>,
                         cudaFuncAttributeMaxDynamicSharedMemorySize, SM2);

    const int TB = 256;

    int nodeBlk = (N * 32 + TB - 1) / TB;
    int gemmBlk = (N + RBLK - 1) / RBLK;
    int nb = (N + SCAN_BLK - 1) / SCAN_BLK;

    // Launch order note: the ncu capture lands on the 4th kernel launch, so
    // gemm1 (independent of the CSR chain) is deliberately placed at slot 4.
    detect_kernel<<<1, 32>>>((const int*)ei);                          // 1
    init_kernel<<<(N + TB - 1) / TB, TB>>>(N);                         // 2
    hist_kernel<<<(E + TB - 1) / TB, TB>>>(ei, E);                     // 3
    gemm_scores_kernel<F_IN, 8><<<gemmBlk, 512, SM1>>>(
        x, W1, as1, ad1, pH1, pS1s, pS1d, N);                          // 4 <- profiled
    scan_part_kernel<<<nb, SCAN_BLK>>>(N);                             // 5
    scan_mid_kernel<<<1, SCAN_BLK>>>(nb);                              // 6
    scan_final_kernel<<<nb, SCAN_BLK>>>(N, E);                         // 7
    scatter_kernel<<<(E + TB - 1) / TB, TB>>>(ei, E);                  // 8
    aggregate_kernel<8, true><<<nodeBlk, TB>>>(pH1, pS1s, pS1d, b1, pG, N);   // 9
    gemm_scores_kernel<F_HID, 1><<<gemmBlk, 512, SM2>>>(
        pG, W2, as2, ad2, pH2, pS2s, pS2d, N);                         // 10
    aggregate_kernel<1, false><<<nodeBlk, TB>>>(pH2, pS2s, pS2d, b2, out, N); // 11
}

// round 14
// speedup vs baseline: 1.4943x; 1.0457x over previous
#include <cuda_runtime.h>

#define MAXN 50000
#define MAXE 1000000
#define F_IN 300
#define F_HID 64

typedef unsigned long long ull;

// ---------------- scratch (static device globals; no allocation allowed) ----
__device__ float g_H1[MAXN * 64];
__device__ float g_G [MAXN * 64];
__device__ float g_H2[MAXN * 64];
__device__ float g_ssrc1[MAXN * 8];
__device__ float g_sdst1[MAXN * 8];
__device__ float g_ssrc2[MAXN];
__device__ float g_sdst2[MAXN];
__device__ int   g_cnt[MAXN];
__device__ int   g_rowoff[MAXN + 1];
__device__ int   g_cursor[MAXN];
__device__ int   g_colsrc[MAXE];
__device__ int   g_part[256];
__device__ int   g_partoff[256];
__device__ int   g_idx64;

// ---------------- packed f32x2 helpers ---------------------------------------
__device__ __forceinline__ ull bc2(float x) {
    ull r; unsigned u = __float_as_uint(x);
    asm("mov.b64 %0, {%1, %1};" : "=l"(r) : "r"(u));
    return r;
}
__device__ __forceinline__ void fma2(ull& a, ull x, ull w) {
    asm("fma.rn.f32x2 %0, %1, %2, %0;" : "+l"(a) : "l"(x), "l"(w));
}
__device__ __forceinline__ float2 unpack2(ull a) {
    return make_float2(__uint_as_float((unsigned)a),
                       __uint_as_float((unsigned)(a >> 32)));
}

// ---------------- cp.async helpers -------------------------------------------
__device__ __forceinline__ unsigned su32(const void* p) {
    return (unsigned)__cvta_generic_to_shared(p);
}
__device__ __forceinline__ void cpa16(unsigned dst, const void* src) {
    asm volatile("cp.async.cg.shared.global [%0], [%1], 16;" :: "r"(dst), "l"(src));
}
__device__ __forceinline__ void cpa_commit() {
    asm volatile("cp.async.commit_group;");
}
template <int n>
__device__ __forceinline__ void cpa_wait() {
    asm volatile("cp.async.wait_group %0;" :: "n"(n));
}

// ---------------- edge index access (dtype-agnostic) ------------------------
__device__ __forceinline__ int eidx(const void* ei, int pos) {
    if (g_idx64) return (int)((const long long*)ei)[pos];
    return ((const int*)ei)[pos];
}

__global__ void detect_kernel(const int* ei32) {
    if (threadIdx.x == 0 && blockIdx.x == 0) {
        int allz = 1;
        #pragma unroll
        for (int i = 0; i < 16; i++)
            if (ei32[2 * i + 1] != 0) allz = 0;
        g_idx64 = allz;
    }
}

// ---------------- CSR build --------------------------------------------------
__global__ void init_kernel(int N) {
    int i = blockIdx.x * blockDim.x + threadIdx.x;
    if (i < N) { g_cnt[i] = 0; g_cursor[i] = 0; }
}

__global__ void hist_kernel(const void* ei, int E) {
    int i = blockIdx.x * blockDim.x + threadIdx.x;
    if (i < E) {
        int d = eidx(ei, E + i);
        atomicAdd(&g_cnt[d], 1);
    }
}

#define SCAN_BLK 256
__global__ void scan_part_kernel(int N) {
    __shared__ int sh[SCAN_BLK];
    int t = threadIdx.x;
    int i = blockIdx.x * SCAN_BLK + t;
    sh[t] = (i < N) ? g_cnt[i] : 0;
    __syncthreads();
    for (int o = SCAN_BLK / 2; o > 0; o >>= 1) {
        if (t < o) sh[t] += sh[t + o];
        __syncthreads();
    }
    if (t == 0) g_part[blockIdx.x] = sh[0];
}

__global__ void scan_mid_kernel(int nb) {
    __shared__ int sh[SCAN_BLK];
    int t = threadIdx.x;
    int v = (t < nb) ? g_part[t] : 0;
    sh[t] = v;
    __syncthreads();
    for (int o = 1; o < SCAN_BLK; o <<= 1) {
        int u = (t >= o) ? sh[t - o] : 0;
        __syncthreads();
        sh[t] += u;
        __syncthreads();
    }
    g_partoff[t] = sh[t] - v;
}

__global__ void scan_final_kernel(int N, int E) {
    __shared__ int sh[SCAN_BLK];
    int t = threadIdx.x;
    int i = blockIdx.x * SCAN_BLK + t;
    int v = (i < N) ? g_cnt[i] : 0;
    sh[t] = v;
    __syncthreads();
    for (int o = 1; o < SCAN_BLK; o <<= 1) {
        int u = (t >= o) ? sh[t - o] : 0;
        __syncthreads();
        sh[t] += u;
        __syncthreads();
    }
    if (i < N) g_rowoff[i] = g_partoff[blockIdx.x] + sh[t] - v;
    if (i == 0) g_rowoff[N] = E;
}

__global__ void scatter_kernel(const void* ei, int E) {
    int i = blockIdx.x * blockDim.x + threadIdx.x;
    if (i < E) {
        int s = eidx(ei, i);
        int d = eidx(ei, E + i);
        int p = atomicAdd(&g_cursor[d], 1);
        g_colsrc[g_rowoff[d] + p] = s;
    }
}

// ---------------- pipelined GEMM + attention logits ---------------------------
// H[N,64] = X[N,K] @ W[K,64] + fused per-head scores.
// 512 threads / block, 128 rows / block (8 rows per warp).
// BARRIER-FREE mainloop: each warp cp.asyncs its OWN 8 rows x 32-k stage into
// warp-private smem (1KB/stage); wait_group is per-thread, so __syncwarp
// replaces the two block barriers per chunk of R12 (occ was fine at 43%, issue
// stuck at 48% -> barrier/wait skew was the residual).
#define GSTG 2
template <int K, int HEADS>
__global__ __launch_bounds__(512, 2)
void gemm_scores_kernel(const float* __restrict__ X,
                        const float* __restrict__ W,
                        const float* __restrict__ avs,
                        const float* __restrict__ avd,
                        float* __restrict__ Hout,
                        float* __restrict__ ssrc,
                        float* __restrict__ sdst, int N) {
    constexpr int NC = (K + 31) / 32;                  // 32-k chunks
    extern __shared__ float smem[];
    float*  sW = smem;                                 // K*64 floats
    float4* sX = (float4*)(smem + K * 64);             // [16 warps][GSTG][8 rows][8 f4]

    int tid = threadIdx.x, warp = tid >> 5, lane = tid & 31;
    int rowBase = blockIdx.x * 128;
    int row0 = rowBase + warp * 8;

    // W async load -> commit group 0 (all threads cooperate)
    for (int i = tid; i < K * 16; i += 512)
        cpa16(su32(sW) + i * 16, (const char*)W + (size_t)i * 16);
    cpa_commit();

    // per-warp x loader: lane covers row (lane>>2), 32B segment (lane&3)
    int lrow = lane >> 2;
    int lseg = lane & 3;
    const char* xr = (const char*)(X + (size_t)min(row0 + lrow, N - 1) * K);
    unsigned wbase = su32(sX) + (unsigned)(warp * GSTG * 64) * 16u;

    auto load_stage = [&](int s) {
        if (s >= NC) return;
        int kb  = s * 32;
        int nf4 = min(8, (K - kb + 3) >> 2);
        unsigned dst = wbase + (unsigned)((s % GSTG) * 64 + lrow * 8) * 16u;
        int j0 = lseg * 2, j1 = lseg * 2 + 1;
        if (j0 < nf4) cpa16(dst + j0 * 16, xr + (size_t)kb * 4 + j0 * 16);
        if (j1 < nf4) cpa16(dst + j1 * 16, xr + (size_t)kb * 4 + j1 * 16);
    };
    load_stage(0); cpa_commit();   // group 1
    load_stage(1); cpa_commit();   // group 2

    cpa_wait<1>();                 // W + stage0 landed (per thread)
    __syncthreads();               // W visible block-wide (only barrier)

    ull acc[8];
    #pragma unroll
    for (int i = 0; i < 8; i++) acc[i] = 0;
    const ull* wl = (const ull*)sW + lane;
    const float4* mySX = sX + warp * GSTG * 64;

    for (int c = 0; c < NC; c++) {
        if (c) { cpa_wait<1>(); __syncwarp(); }   // stage c landed, warp-visible
        int kb = c * 32;
        int nq = min(8, (K - kb) >> 2);
        const float4* sxs = mySX + (c % GSTG) * 64;
        #pragma unroll 2
        for (int q = 0; q < nq; q++) {
            int k0 = kb + 4 * q;
            ull w0 = wl[(k0 + 0) * 32];
            ull w1 = wl[(k0 + 1) * 32];
            ull w2 = wl[(k0 + 2) * 32];
            ull w3 = wl[(k0 + 3) * 32];
            #pragma unroll
            for (int i = 0; i < 8; i++) {
                float4 v = sxs[i * 8 + q];
                fma2(acc[i], bc2(v.x), w0);
                fma2(acc[i], bc2(v.y), w1);
                fma2(acc[i], bc2(v.z), w2);
                fma2(acc[i], bc2(v.w), w3);
            }
        }
        __syncwarp();              // all lanes done reading slot before refill
        load_stage(c + GSTG);
        cpa_commit();              // exactly one group per iteration
    }

    if (row0 >= N) return;
    float2 as = *(const float2*)(avs + 2 * lane);
    float2 ad = *(const float2*)(avd + 2 * lane);

    #pragma unroll
    for (int i = 0; i < 8; i++) {
        int row = row0 + i;
        if (row >= N) break;
        float2 r = unpack2(acc[i]);
        *(float2*)(Hout + (size_t)row * 64 + 2 * lane) = r;
        float vs = r.x * as.x + r.y * as.y;
        float vd = r.x * ad.x + r.y * ad.y;
        if (HEADS == 8) {
            vs += __shfl_xor_sync(0xffffffffu, vs, 1);
            vd += __shfl_xor_sync(0xffffffffu, vd, 1);
            vs += __shfl_xor_sync(0xffffffffu, vs, 2);
            vd += __shfl_xor_sync(0xffffffffu, vd, 2);
            if ((lane & 3) == 0) {
                ssrc[row * 8 + (lane >> 2)] = vs;
                sdst[row * 8 + (lane >> 2)] = vd;
            }
        } else {
            #pragma unroll
            for (int o = 1; o < 32; o <<= 1) {
                vs += __shfl_xor_sync(0xffffffffu, vs, o);
                vd += __shfl_xor_sync(0xffffffffu, vd, o);
            }
            if (lane == 0) { ssrc[row] = vs; sdst[row] = vd; }
        }
    }
}

// ---------------- segment-softmax + aggregation -------------------------------
// One warp per destination node.  Phase A: edge-parallel logits into smem.
// Phase B: per-lane max, then MLP-4 unrolled weighted gather of h rows (4
// independent LDG.64 in flight per lane to cover L2 latency).
#define CAP 64
template <int HEADS, bool ELU>
__global__ void aggregate_kernel(const float* __restrict__ Hf,
                                 const float* __restrict__ ssrc,
                                 const float* __restrict__ sdst,
                                 const float* __restrict__ bias,
                                 float* __restrict__ out, int N) {
    __shared__ float sE[8][CAP * HEADS];
    __shared__ int   sS[8][CAP];
    int gt = blockIdx.x * blockDim.x + threadIdx.x;
    int n = gt >> 5, lane = gt & 31;
    if (n >= N) return;
    int wI = threadIdx.x >> 5;
    int head = (HEADS == 8) ? (lane >> 2) : 0;
    int beg = g_rowoff[n], end = g_rowoff[n + 1];
    int deg = end - beg;
    float* se = sE[wI];
    int*   ss = sS[wI];

    float sw = 0.f, ax = 0.f, ay = 0.f;

    if (deg <= CAP) {
        if (HEADS == 8) {
            float4 d0 = *(const float4*)(sdst + (size_t)n * 8);
            float4 d1 = *(const float4*)(sdst + (size_t)n * 8 + 4);
            #pragma unroll
            for (int base = 0; base < CAP; base += 32) {
                int j = base + lane;
                if (j < deg) {
                    int s = __ldg(&g_colsrc[beg + j]);
                    ss[j] = s;
                    float4 s0 = __ldg((const float4*)(ssrc + (size_t)s * 8));
                    float4 s1 = __ldg((const float4*)(ssrc + (size_t)s * 8 + 4));
                    float e;
                    e = s0.x + d0.x; se[j * 8 + 0] = fmaxf(e, 0.2f * e);
                    e = s0.y + d0.y; se[j * 8 + 1] = fmaxf(e, 0.2f * e);
                    e = s0.z + d0.z; se[j * 8 + 2] = fmaxf(e, 0.2f * e);
                    e = s0.w + d0.w; se[j * 8 + 3] = fmaxf(e, 0.2f * e);
                    e = s1.x + d1.x; se[j * 8 + 4] = fmaxf(e, 0.2f * e);
                    e = s1.y + d1.y; se[j * 8 + 5] = fmaxf(e, 0.2f * e);
                    e = s1.z + d1.z; se[j * 8 + 6] = fmaxf(e, 0.2f * e);
                    e = s1.w + d1.w; se[j * 8 + 7] = fmaxf(e, 0.2f * e);
                }
            }
        } else {
            float sd = __ldg(&sdst[n]);
            #pragma unroll
            for (int base = 0; base < CAP; base += 32) {
                int j = base + lane;
                if (j < deg) {
                    int s = __ldg(&g_colsrc[beg + j]);
                    ss[j] = s;
                    float e = __ldg(&ssrc[s]) + sd;
                    se[j] = fmaxf(e, 0.2f * e);
                }
            }
        }
        __syncwarp();

        float m = -1e30f;
        for (int j = 0; j < deg; j++)
            m = fmaxf(m, se[j * HEADS + head]);

        const float* Hb = Hf + 2 * lane;
        int j = 0;
        for (; j + 4 <= deg; j += 4) {         // MLP-4: 4 gathers in flight
            int s0 = ss[j], s1 = ss[j + 1], s2 = ss[j + 2], s3 = ss[j + 3];
            float2 h0 = *(const float2*)(Hb + (size_t)s0 * 64);
            float2 h1 = *(const float2*)(Hb + (size_t)s1 * 64);
            float2 h2 = *(const float2*)(Hb + (size_t)s2 * 64);
            float2 h3 = *(const float2*)(Hb + (size_t)s3 * 64);
            float w0 = __expf(se[(j + 0) * HEADS + head] - m);
            float w1 = __expf(se[(j + 1) * HEADS + head] - m);
            float w2 = __expf(se[(j + 2) * HEADS + head] - m);
            float w3 = __expf(se[(j + 3) * HEADS + head] - m);
            sw += w0 + w1 + w2 + w3;
            ax = fmaf(h0.x, w0, ax); ay = fmaf(h0.y, w0, ay);
            ax = fmaf(h1.x, w1, ax); ay = fmaf(h1.y, w1, ay);
            ax = fmaf(h2.x, w2, ax); ay = fmaf(h2.y, w2, ay);
            ax = fmaf(h3.x, w3, ax); ay = fmaf(h3.y, w3, ay);
        }
        for (; j < deg; j++) {
            float w = __expf(se[j * HEADS + head] - m);
            float2 hv = *(const float2*)(Hb + (size_t)ss[j] * 64);
            sw += w;
            ax = fmaf(hv.x, w, ax);
            ay = fmaf(hv.y, w, ay);
        }
    } else {
        float sd = sdst[n * HEADS + head];
        float m = -1e30f;
        for (int j = beg; j < end; j++) {
            int s = __ldg(&g_colsrc[j]);
            float e = __ldg(&ssrc[s * HEADS + head]) + sd;
            m = fmaxf(m, fmaxf(e, 0.2f * e));
        }
        for (int j = beg; j < end; j++) {
            int s = __ldg(&g_colsrc[j]);
            float e = __ldg(&ssrc[s * HEADS + head]) + sd;
            e = fmaxf(e, 0.2f * e);
            float w = __expf(e - m);
            float2 hv = *(const float2*)(Hf + (size_t)s * 64 + 2 * lane);
            sw += w;
            ax = fmaf(hv.x, w, ax);
            ay = fmaf(hv.y, w, ay);
        }
    }

    float inv = 1.f / (sw + 1e-16f);
    float2 bv = *(const float2*)(bias + 2 * lane);
    float o0 = ax * inv + bv.x;
    float o1 = ay * inv + bv.y;
    if (ELU) {
        o0 = (o0 > 0.f) ? o0 : (__expf(o0) - 1.f);
        o1 = (o1 > 0.f) ? o1 : (__expf(o1) - 1.f);
    }
    *(float2*)(out + (size_t)n * 64 + 2 * lane) = make_float2(o0, o1);
}

// ---------------- launch -----------------------------------------------------
extern "C" void kernel_launch(void* const* d_in, const int* in_sizes, int n_in,
                              void* d_out, int out_size) {
    const float* x   = (const float*)d_in[0];
    const void*  ei  = d_in[1];
    const float* W1  = (const float*)d_in[2];
    const float* as1 = (const float*)d_in[3];
    const float* ad1 = (const float*)d_in[4];
    const float* b1  = (const float*)d_in[5];
    const float* W2  = (const float*)d_in[6];
    const float* as2 = (const float*)d_in[7];
    const float* ad2 = (const float*)d_in[8];
    const float* b2  = (const float*)d_in[9];
    float* out = (float*)d_out;

    int N = in_sizes[0] / F_IN;
    int E = in_sizes[1] / 2;

    float *pH1, *pG, *pH2, *pS1s, *pS1d, *pS2s, *pS2d;
    cudaGetSymbolAddress((void**)&pH1,  g_H1);
    cudaGetSymbolAddress((void**)&pG,   g_G);
    cudaGetSymbolAddress((void**)&pH2,  g_H2);
    cudaGetSymbolAddress((void**)&pS1s, g_ssrc1);
    cudaGetSymbolAddress((void**)&pS1d, g_sdst1);
    cudaGetSymbolAddress((void**)&pS2s, g_ssrc2);
    cudaGetSymbolAddress((void**)&pS2d, g_sdst2);

    const int SM1 = F_IN  * 64 * 4 + 16 * GSTG * 64 * 16;   // 109568 B
    const int SM2 = F_HID * 64 * 4 + 16 * GSTG * 64 * 16;   //  49152 B
    cudaFuncSetAttribute(gemm_scores_kernel<F_IN, 8>,
                         cudaFuncAttributeMaxDynamicSharedMemorySize, SM1);
    cudaFuncSetAttribute(gemm_scores_kernel<F_HID, 1>,
                         cudaFuncAttributeMaxDynamicSharedMemorySize, SM2);

    const int TB = 256;

    int nodeBlk = (N * 32 + TB - 1) / TB;
    int gemmBlk = (N + 127) / 128;
    int nb = (N + SCAN_BLK - 1) / SCAN_BLK;

    // Launch order note: the ncu capture lands on the 4th kernel launch, so
    // gemm1 (independent of the CSR chain) is deliberately placed at slot 4.
    detect_kernel<<<1, 32>>>((const int*)ei);                          // 1
    init_kernel<<<(N + TB - 1) / TB, TB>>>(N);                         // 2
    hist_kernel<<<(E + TB - 1) / TB, TB>>>(ei, E);                     // 3
    gemm_scores_kernel<F_IN, 8><<<gemmBlk, 512, SM1>>>(
        x, W1, as1, ad1, pH1, pS1s, pS1d, N);                          // 4 <- profiled
    scan_part_kernel<<<nb, SCAN_BLK>>>(N);                             // 5
    scan_mid_kernel<<<1, SCAN_BLK>>>(nb);                              // 6
    scan_final_kernel<<<nb, SCAN_BLK>>>(N, E);                         // 7
    scatter_kernel<<<(E + TB - 1) / TB, TB>>>(ei, E);                  // 8
    aggregate_kernel<8, true><<<nodeBlk, TB>>>(pH1, pS1s, pS1d, b1, pG, N);   // 9
    gemm_scores_kernel<F_HID, 1><<<gemmBlk, 512, SM2>>>(
        pG, W2, as2, ad2, pH2, pS2s, pS2d, N);                         // 10
    aggregate_kernel<1, false><<<nodeBlk, TB>>>(pH2, pS2s, pS2d, b2, out, N); // 11
}

// round 15
// speedup vs baseline: 1.5004x; 1.0041x over previous
#include <cuda_runtime.h>

#define MAXN 50000
#define MAXE 1000000
#define F_IN 300
#define F_HID 64

typedef unsigned long long ull;

// ---------------- scratch (static device globals; no allocation allowed) ----
__device__ float g_H1[MAXN * 64];
__device__ float g_G [MAXN * 64];
__device__ float g_H2[MAXN * 64];
__device__ float g_ssrc1[MAXN * 8];
__device__ float g_sdst1[MAXN * 8];
__device__ float g_ssrc2[MAXN];
__device__ float g_sdst2[MAXN];
__device__ int   g_cnt[MAXN];
__device__ int   g_rowoff[MAXN + 1];
__device__ int   g_cursor[MAXN];
__device__ int   g_colsrc[MAXE];
__device__ int   g_part[256];
__device__ int   g_partoff[256];
__device__ int   g_idx64;

// ---------------- packed f32x2 helpers ---------------------------------------
__device__ __forceinline__ ull bc2(float x) {
    ull r; unsigned u = __float_as_uint(x);
    asm("mov.b64 %0, {%1, %1};" : "=l"(r) : "r"(u));
    return r;
}
__device__ __forceinline__ void fma2(ull& a, ull x, ull w) {
    asm("fma.rn.f32x2 %0, %1, %2, %0;" : "+l"(a) : "l"(x), "l"(w));
}
__device__ __forceinline__ float2 unpack2(ull a) {
    return make_float2(__uint_as_float((unsigned)a),
                       __uint_as_float((unsigned)(a >> 32)));
}

// ---------------- cp.async helpers -------------------------------------------
__device__ __forceinline__ unsigned su32(const void* p) {
    return (unsigned)__cvta_generic_to_shared(p);
}
__device__ __forceinline__ void cpa16(unsigned dst, const void* src) {
    asm volatile("cp.async.cg.shared.global [%0], [%1], 16;" :: "r"(dst), "l"(src));
}
__device__ __forceinline__ void cpa_commit() {
    asm volatile("cp.async.commit_group;");
}
template <int n>
__device__ __forceinline__ void cpa_wait() {
    asm volatile("cp.async.wait_group %0;" :: "n"(n));
}

// ---------------- edge index access (dtype-agnostic) ------------------------
__device__ __forceinline__ int eidx(const void* ei, int pos) {
    if (g_idx64) return (int)((const long long*)ei)[pos];
    return ((const int*)ei)[pos];
}

__global__ void detect_kernel(const int* ei32) {
    if (threadIdx.x == 0 && blockIdx.x == 0) {
        int allz = 1;
        #pragma unroll
        for (int i = 0; i < 16; i++)
            if (ei32[2 * i + 1] != 0) allz = 0;
        g_idx64 = allz;
    }
}

// ---------------- CSR build --------------------------------------------------
__global__ void init_kernel(int N) {
    int i = blockIdx.x * blockDim.x + threadIdx.x;
    if (i < N) { g_cnt[i] = 0; g_cursor[i] = 0; }
}

__global__ void hist_kernel(const void* ei, int E) {
    int i = blockIdx.x * blockDim.x + threadIdx.x;
    if (i < E) {
        int d = eidx(ei, E + i);
        atomicAdd(&g_cnt[d], 1);
    }
}

#define SCAN_BLK 256
__global__ void scan_part_kernel(int N) {
    __shared__ int sh[SCAN_BLK];
    int t = threadIdx.x;
    int i = blockIdx.x * SCAN_BLK + t;
    sh[t] = (i < N) ? g_cnt[i] : 0;
    __syncthreads();
    for (int o = SCAN_BLK / 2; o > 0; o >>= 1) {
        if (t < o) sh[t] += sh[t + o];
        __syncthreads();
    }
    if (t == 0) g_part[blockIdx.x] = sh[0];
}

__global__ void scan_mid_kernel(int nb) {
    __shared__ int sh[SCAN_BLK];
    int t = threadIdx.x;
    int v = (t < nb) ? g_part[t] : 0;
    sh[t] = v;
    __syncthreads();
    for (int o = 1; o < SCAN_BLK; o <<= 1) {
        int u = (t >= o) ? sh[t - o] : 0;
        __syncthreads();
        sh[t] += u;
        __syncthreads();
    }
    g_partoff[t] = sh[t] - v;
}

__global__ void scan_final_kernel(int N, int E) {
    __shared__ int sh[SCAN_BLK];
    int t = threadIdx.x;
    int i = blockIdx.x * SCAN_BLK + t;
    int v = (i < N) ? g_cnt[i] : 0;
    sh[t] = v;
    __syncthreads();
    for (int o = 1; o < SCAN_BLK; o <<= 1) {
        int u = (t >= o) ? sh[t - o] : 0;
        __syncthreads();
        sh[t] += u;
        __syncthreads();
    }
    if (i < N) g_rowoff[i] = g_partoff[blockIdx.x] + sh[t] - v;
    if (i == 0) g_rowoff[N] = E;
}

__global__ void scatter_kernel(const void* ei, int E) {
    int i = blockIdx.x * blockDim.x + threadIdx.x;
    if (i < E) {
        int s = eidx(ei, i);
        int d = eidx(ei, E + i);
        int p = atomicAdd(&g_cursor[d], 1);
        g_colsrc[g_rowoff[d] + p] = s;
    }
}

// ---------------- pipelined GEMM + attention logits ---------------------------
// H[N,64] = X[N,K] @ W[K,64] + fused per-head scores.
// 256 threads / block (8 warps), 16 rows / warp = 128 rows / block.
// W smem reads are irreducible at 256B/k/warp; 16 rows amortizes them over
// 64 FFMA2 per quad (vs 32 at 8 rows), shifting the bottleneck from LSU
// (R14: L1=72%) to the fma pipe.  2 blocks x 256 thr = 512 thr/SM -> 128-reg
// budget, so the 16-ull accumulator set stays in registers.
#define GSTG 2
#define WR 16   // rows per warp
template <int K, int HEADS>
__global__ __launch_bounds__(256, 2)
void gemm_scores_kernel(const float* __restrict__ X,
                        const float* __restrict__ W,
                        const float* __restrict__ avs,
                        const float* __restrict__ avd,
                        float* __restrict__ Hout,
                        float* __restrict__ ssrc,
                        float* __restrict__ sdst, int N) {
    constexpr int NC = (K + 31) / 32;                  // 32-k chunks
    extern __shared__ float smem[];
    float*  sW = smem;                                 // K*64 floats
    float4* sX = (float4*)(smem + K * 64);             // [8 warps][GSTG][16 rows][8 f4]

    int tid = threadIdx.x, warp = tid >> 5, lane = tid & 31;
    int rowBase = blockIdx.x * 128;
    int row0 = rowBase + warp * WR;

    // W async load -> commit group 0 (all threads cooperate)
    for (int i = tid; i < K * 16; i += 256)
        cpa16(su32(sW) + i * 16, (const char*)W + (size_t)i * 16);
    cpa_commit();

    // per-warp x loader: lane covers row (lane>>1), float4 group (lane&1)*4..+3
    int lrow = lane >> 1;
    int lseg = lane & 1;
    const char* xr = (const char*)(X + (size_t)min(row0 + lrow, N - 1) * K);
    unsigned wbase = su32(sX) + (unsigned)(warp * GSTG * WR * 8) * 16u;

    auto load_stage = [&](int s) {
        if (s >= NC) return;
        int kb  = s * 32;
        int nf4 = min(8, (K - kb + 3) >> 2);
        unsigned dst = wbase + (unsigned)((s % GSTG) * WR * 8 + lrow * 8) * 16u;
        #pragma unroll
        for (int jj = 0; jj < 4; jj++) {
            int j = lseg * 4 + jj;
            if (j < nf4) cpa16(dst + j * 16, xr + (size_t)kb * 4 + j * 16);
        }
    };
    load_stage(0); cpa_commit();   // group 1
    load_stage(1); cpa_commit();   // group 2

    cpa_wait<1>();                 // W + stage0 landed (per thread)
    __syncthreads();               // W visible block-wide (only barrier)

    ull acc[WR];
    #pragma unroll
    for (int i = 0; i < WR; i++) acc[i] = 0;
    const ull* wl = (const ull*)sW + lane;
    const float4* mySX = sX + warp * GSTG * WR * 8;

    for (int c = 0; c < NC; c++) {
        if (c) { cpa_wait<1>(); __syncwarp(); }   // stage c landed, warp-visible
        int kb = c * 32;
        int nq = min(8, (K - kb) >> 2);
        const float4* sxs = mySX + (c % GSTG) * WR * 8;
        for (int q = 0; q < nq; q++) {
            int k0 = kb + 4 * q;
            ull w0 = wl[(k0 + 0) * 32];
            ull w1 = wl[(k0 + 1) * 32];
            ull w2 = wl[(k0 + 2) * 32];
            ull w3 = wl[(k0 + 3) * 32];
            #pragma unroll
            for (int i = 0; i < WR; i++) {
                float4 v = sxs[i * 8 + q];
                fma2(acc[i], bc2(v.x), w0);
                fma2(acc[i], bc2(v.y), w1);
                fma2(acc[i], bc2(v.z), w2);
                fma2(acc[i], bc2(v.w), w3);
            }
        }
        __syncwarp();              // all lanes done reading slot before refill
        load_stage(c + GSTG);
        cpa_commit();              // exactly one group per iteration
    }

    if (row0 >= N) return;
    float2 as = *(const float2*)(avs + 2 * lane);
    float2 ad = *(const float2*)(avd + 2 * lane);

    #pragma unroll
    for (int i = 0; i < WR; i++) {
        int row = row0 + i;
        if (row >= N) break;
        float2 r = unpack2(acc[i]);
        *(float2*)(Hout + (size_t)row * 64 + 2 * lane) = r;
        float vs = r.x * as.x + r.y * as.y;
        float vd = r.x * ad.x + r.y * ad.y;
        if (HEADS == 8) {
            vs += __shfl_xor_sync(0xffffffffu, vs, 1);
            vd += __shfl_xor_sync(0xffffffffu, vd, 1);
            vs += __shfl_xor_sync(0xffffffffu, vs, 2);
            vd += __shfl_xor_sync(0xffffffffu, vd, 2);
            if ((lane & 3) == 0) {
                ssrc[row * 8 + (lane >> 2)] = vs;
                sdst[row * 8 + (lane >> 2)] = vd;
            }
        } else {
            #pragma unroll
            for (int o = 1; o < 32; o <<= 1) {
                vs += __shfl_xor_sync(0xffffffffu, vs, o);
                vd += __shfl_xor_sync(0xffffffffu, vd, o);
            }
            if (lane == 0) { ssrc[row] = vs; sdst[row] = vd; }
        }
    }
}

// ---------------- segment-softmax + aggregation -------------------------------
// One warp per destination node.  Phase A: edge-parallel logits into smem.
// Phase B: per-lane max, then MLP-8 unrolled weighted gather of h rows (8
// independent LDG.64 in flight per lane to cover L2 latency).
#define CAP 64
template <int HEADS, bool ELU>
__global__ void aggregate_kernel(const float* __restrict__ Hf,
                                 const float* __restrict__ ssrc,
                                 const float* __restrict__ sdst,
                                 const float* __restrict__ bias,
                                 float* __restrict__ out, int N) {
    __shared__ float sE[8][CAP * HEADS];
    __shared__ int   sS[8][CAP];
    int gt = blockIdx.x * blockDim.x + threadIdx.x;
    int n = gt >> 5, lane = gt & 31;
    if (n >= N) return;
    int wI = threadIdx.x >> 5;
    int head = (HEADS == 8) ? (lane >> 2) : 0;
    int beg = g_rowoff[n], end = g_rowoff[n + 1];
    int deg = end - beg;
    float* se = sE[wI];
    int*   ss = sS[wI];

    float sw = 0.f, ax = 0.f, ay = 0.f;

    if (deg <= CAP) {
        if (HEADS == 8) {
            float4 d0 = *(const float4*)(sdst + (size_t)n * 8);
            float4 d1 = *(const float4*)(sdst + (size_t)n * 8 + 4);
            #pragma unroll
            for (int base = 0; base < CAP; base += 32) {
                int j = base + lane;
                if (j < deg) {
                    int s = __ldg(&g_colsrc[beg + j]);
                    ss[j] = s;
                    float4 s0 = __ldg((const float4*)(ssrc + (size_t)s * 8));
                    float4 s1 = __ldg((const float4*)(ssrc + (size_t)s * 8 + 4));
                    float e;
                    e = s0.x + d0.x; se[j * 8 + 0] = fmaxf(e, 0.2f * e);
                    e = s0.y + d0.y; se[j * 8 + 1] = fmaxf(e, 0.2f * e);
                    e = s0.z + d0.z; se[j * 8 + 2] = fmaxf(e, 0.2f * e);
                    e = s0.w + d0.w; se[j * 8 + 3] = fmaxf(e, 0.2f * e);
                    e = s1.x + d1.x; se[j * 8 + 4] = fmaxf(e, 0.2f * e);
                    e = s1.y + d1.y; se[j * 8 + 5] = fmaxf(e, 0.2f * e);
                    e = s1.z + d1.z; se[j * 8 + 6] = fmaxf(e, 0.2f * e);
                    e = s1.w + d1.w; se[j * 8 + 7] = fmaxf(e, 0.2f * e);
                }
            }
        } else {
            float sd = __ldg(&sdst[n]);
            #pragma unroll
            for (int base = 0; base < CAP; base += 32) {
                int j = base + lane;
                if (j < deg) {
                    int s = __ldg(&g_colsrc[beg + j]);
                    ss[j] = s;
                    float e = __ldg(&ssrc[s]) + sd;
                    se[j] = fmaxf(e, 0.2f * e);
                }
            }
        }
        __syncwarp();

        float m = -1e30f;
        for (int j = 0; j < deg; j++)
            m = fmaxf(m, se[j * HEADS + head]);

        const float* Hb = Hf + 2 * lane;
        int j = 0;
        for (; j + 8 <= deg; j += 8) {         // MLP-8: 8 gathers in flight
            float2 h[8];
            float  w[8];
            #pragma unroll
            for (int u = 0; u < 8; u++)
                h[u] = *(const float2*)(Hb + (size_t)ss[j + u] * 64);
            #pragma unroll
            for (int u = 0; u < 8; u++)
                w[u] = __expf(se[(j + u) * HEADS + head] - m);
            #pragma unroll
            for (int u = 0; u < 8; u++) {
                sw += w[u];
                ax = fmaf(h[u].x, w[u], ax);
                ay = fmaf(h[u].y, w[u], ay);
            }
        }
        for (; j < deg; j++) {
            float w = __expf(se[j * HEADS + head] - m);
            float2 hv = *(const float2*)(Hb + (size_t)ss[j] * 64);
            sw += w;
            ax = fmaf(hv.x, w, ax);
            ay = fmaf(hv.y, w, ay);
        }
    } else {
        float sd = sdst[n * HEADS + head];
        float m = -1e30f;
        for (int j = beg; j < end; j++) {
            int s = __ldg(&g_colsrc[j]);
            float e = __ldg(&ssrc[s * HEADS + head]) + sd;
            m = fmaxf(m, fmaxf(e, 0.2f * e));
        }
        for (int j = beg; j < end; j++) {
            int s = __ldg(&g_colsrc[j]);
            float e = __ldg(&ssrc[s * HEADS + head]) + sd;
            e = fmaxf(e, 0.2f * e);
            float w = __expf(e - m);
            float2 hv = *(const float2*)(Hf + (size_t)s * 64 + 2 * lane);
            sw += w;
            ax = fmaf(hv.x, w, ax);
            ay = fmaf(hv.y, w, ay);
        }
    }

    float inv = 1.f / (sw + 1e-16f);
    float2 bv = *(const float2*)(bias + 2 * lane);
    float o0 = ax * inv + bv.x;
    float o1 = ay * inv + bv.y;
    if (ELU) {
        o0 = (o0 > 0.f) ? o0 : (__expf(o0) - 1.f);
        o1 = (o1 > 0.f) ? o1 : (__expf(o1) - 1.f);
    }
    *(float2*)(out + (size_t)n * 64 + 2 * lane) = make_float2(o0, o1);
}

// ---------------- launch -----------------------------------------------------
extern "C" void kernel_launch(void* const* d_in, const int* in_sizes, int n_in,
                              void* d_out, int out_size) {
    const float* x   = (const float*)d_in[0];
    const void*  ei  = d_in[1];
    const float* W1  = (const float*)d_in[2];
    const float* as1 = (const float*)d_in[3];
    const float* ad1 = (const float*)d_in[4];
    const float* b1  = (const float*)d_in[5];
    const float* W2  = (const float*)d_in[6];
    const float* as2 = (const float*)d_in[7];
    const float* ad2 = (const float*)d_in[8];
    const float* b2  = (const float*)d_in[9];
    float* out = (float*)d_out;

    int N = in_sizes[0] / F_IN;
    int E = in_sizes[1] / 2;

    float *pH1, *pG, *pH2, *pS1s, *pS1d, *pS2s, *pS2d;
    cudaGetSymbolAddress((void**)&pH1,  g_H1);
    cudaGetSymbolAddress((void**)&pG,   g_G);
    cudaGetSymbolAddress((void**)&pH2,  g_H2);
    cudaGetSymbolAddress((void**)&pS1s, g_ssrc1);
    cudaGetSymbolAddress((void**)&pS1d, g_sdst1);
    cudaGetSymbolAddress((void**)&pS2s, g_ssrc2);
    cudaGetSymbolAddress((void**)&pS2d, g_sdst2);

    // smem: W (K*64*4) + 8 warps * GSTG stages * 16 rows * 128B
    const int SM1 = F_IN  * 64 * 4 + 8 * GSTG * WR * 8 * 16;   // 109568 B
    const int SM2 = F_HID * 64 * 4 + 8 * GSTG * WR * 8 * 16;   //  49152 B
    cudaFuncSetAttribute(gemm_scores_kernel<F_IN, 8>,
                         cudaFuncAttributeMaxDynamicSharedMemorySize, SM1);
    cudaFuncSetAttribute(gemm_scores_kernel<F_HID, 1>,
                         cudaFuncAttributeMaxDynamicSharedMemorySize, SM2);

    const int TB = 256;

    int nodeBlk = (N * 32 + TB - 1) / TB;
    int gemmBlk = (N + 127) / 128;
    int nb = (N + SCAN_BLK - 1) / SCAN_BLK;

    // Launch order note: the ncu capture lands on the 4th kernel launch, so
    // gemm1 (independent of the CSR chain) is deliberately placed at slot 4.
    detect_kernel<<<1, 32>>>((const int*)ei);                          // 1
    init_kernel<<<(N + TB - 1) / TB, TB>>>(N);                         // 2
    hist_kernel<<<(E + TB - 1) / TB, TB>>>(ei, E);                     // 3
    gemm_scores_kernel<F_IN, 8><<<gemmBlk, 256, SM1>>>(
        x, W1, as1, ad1, pH1, pS1s, pS1d, N);                          // 4 <- profiled
    scan_part_kernel<<<nb, SCAN_BLK>>>(N);                             // 5
    scan_mid_kernel<<<1, SCAN_BLK>>>(nb);                              // 6
    scan_final_kernel<<<nb, SCAN_BLK>>>(N, E);                         // 7
    scatter_kernel<<<(E + TB - 1) / TB, TB>>>(ei, E);                  // 8
    aggregate_kernel<8, true><<<nodeBlk, TB>>>(pH1, pS1s, pS1d, b1, pG, N);   // 9
    gemm_scores_kernel<F_HID, 1><<<gemmBlk, 256, SM2>>>(
        pG, W2, as2, ad2, pH2, pS2s, pS2d, N);                         // 10
    aggregate_kernel<1, false><<<nodeBlk, TB>>>(pH2, pS2s, pS2d, b2, out, N); // 11
}